// round 11
// baseline (speedup 1.0000x reference)
#include <cuda_runtime.h>
#include <cuda_fp16.h>
#include <math.h>
#include <stdint.h>

// Problem constants
#define SEQ   4096
#define DM    1024
#define NH    16
#define DH    64

// ---------------- scratch (no allocations allowed) ----------------
// QKV GEMM operands (fp16, 1-pass): x, W (Wq,Wk,Wv stacked rows)
__device__ __half g_x16h[SEQ * DM];
__device__ __half g_w16[3 * DM * DM];
// proj GEMM operands (fp16, 1-pass)
__device__ __half g_w16o[DM * DM];
__device__ __half g_a16h[SEQ * DM];        // attention out (fp16)

// flash operands (fp16), written directly by the QKV epilogue
__device__ __half g_qh[SEQ * DM];   // roped Q, pre-scaled by (1/8)*log2e
__device__ __half g_kh[SEQ * DM];   // roped K
__device__ __half g_vh[SEQ * DM];   // V

// rope table: [s][i*2]=cos, [i*2+1]=sin  (i = 0..31)
__device__ float g_rope[SEQ][64];

// ---------------- low-level helpers ----------------
__device__ __forceinline__ uint32_t smem_u32(const void* p) {
    uint32_t a;
    asm("{ .reg .u64 t; cvta.to.shared.u64 t, %1; cvt.u32.u64 %0, t; }" : "=r"(a) : "l"(p));
    return a;
}
__device__ __forceinline__ void cp_async16(uint32_t sa, const void* ga) {
    asm volatile("cp.async.cg.shared.global [%0], [%1], 16;" :: "r"(sa), "l"(ga));
}
#define CP_COMMIT() asm volatile("cp.async.commit_group;" ::: "memory")
#define CP_WAIT1()  asm volatile("cp.async.wait_group 1;" ::: "memory")
#define CP_WAIT0()  asm volatile("cp.async.wait_group 0;" ::: "memory")

__device__ __forceinline__ void ldsm_x4(uint32_t* r, uint32_t addr) {
    asm volatile("ldmatrix.sync.aligned.m8n8.x4.shared.b16 {%0,%1,%2,%3}, [%4];"
        : "=r"(r[0]), "=r"(r[1]), "=r"(r[2]), "=r"(r[3]) : "r"(addr));
}
__device__ __forceinline__ void ldsm_x4t(uint32_t* r, uint32_t addr) {
    asm volatile("ldmatrix.sync.aligned.m8n8.x4.trans.shared.b16 {%0,%1,%2,%3}, [%4];"
        : "=r"(r[0]), "=r"(r[1]), "=r"(r[2]), "=r"(r[3]) : "r"(addr));
}
__device__ __forceinline__ void ldsm_x2t(uint32_t* r, uint32_t addr) {
    asm volatile("ldmatrix.sync.aligned.m8n8.x2.trans.shared.b16 {%0,%1}, [%2];"
        : "=r"(r[0]), "=r"(r[1]) : "r"(addr));
}
// fp16 mma
__device__ __forceinline__ void mma16816h(float* d, const uint32_t* a, const uint32_t* b) {
    asm volatile("mma.sync.aligned.m16n8k16.row.col.f32.f16.f16.f32 "
        "{%0,%1,%2,%3}, {%4,%5,%6,%7}, {%8,%9}, {%0,%1,%2,%3};"
        : "+f"(d[0]), "+f"(d[1]), "+f"(d[2]), "+f"(d[3])
        : "r"(a[0]), "r"(a[1]), "r"(a[2]), "r"(a[3]), "r"(b[0]), "r"(b[1]));
}
__device__ __forceinline__ uint32_t packh2(__half2 v) {
    uint32_t u; memcpy(&u, &v, 4); return u;
}

// ---------------- fused convert + rope-table kernel (one launch) ----------
// b in [0,4096): x; [4096,7168): Wq/Wk/Wv (stacked); [7168,8192): Wo;
// b in [8192,8704): rope table.
__global__ void cvt_all_kernel(const float* __restrict__ x,
                               const float* __restrict__ Wq,
                               const float* __restrict__ Wk,
                               const float* __restrict__ Wv,
                               const float* __restrict__ Wo) {
    int b = blockIdx.x;
    if (b >= 8192) {
        int idx = (b - 8192) * 256 + threadIdx.x;   // 0..131071
        int s = idx >> 5, i = idx & 31;
        double invf = pow(10000.0, -(2.0 * i) / 64.0);
        double si, co;
        sincos((double)s * invf, &si, &co);
        g_rope[s][i * 2]     = (float)co;
        g_rope[s][i * 2 + 1] = (float)si;
        return;
    }
    const float* src; __half* dst; int si, di;
    if (b < 4096) {
        si = (b * 256 + threadIdx.x) * 4;
        di = si; src = x; dst = g_x16h;
    } else if (b < 7168) {
        int bb = b - 4096;                 // 0..3071
        int mat = bb >> 10;                // 0..2
        src = (mat == 0) ? Wq : (mat == 1 ? Wk : Wv);
        si = ((bb & 1023) * 256 + threadIdx.x) * 4;
        di = (bb * 256 + threadIdx.x) * 4;
        dst = g_w16;
    } else {
        si = ((b - 7168) * 256 + threadIdx.x) * 4;
        di = si; src = Wo; dst = g_w16o;
    }
    float4 v = *(const float4*)&src[si];
    *(uint32_t*)&dst[di]     = packh2(__floats2half2_rn(v.x, v.y));
    *(uint32_t*)&dst[di + 2] = packh2(__floats2half2_rn(v.z, v.w));
}

// ---------------- HMMA fp16 1-pass NT GEMM (3-stage, 1 sync/chunk) ---------
// C[m,n] = sum_k A[m,k]*B[n,k]; BM=BN=128, BK=64, 128 threads, 4 warps of 64x64.
// WHICH=0: QKV; epilogue applies RoPE and stores fp16. WHICH=1: proj -> fp32 out.
#define SKB 144                    // smem row stride bytes (72 elems, conflict-free ldsm)
#define GTILE (128 * SKB)          // 18432 B per matrix tile
#define GSTAGE (2 * GTILE)         // A+B: 36864
#define GEMM_SMEM (3 * GSTAGE)     // 3-stage ring: 110592 (2 CTAs/SM in 228KB)
#define QSCALE 0.18033688011112042f   // 0.125 * log2(e)

__device__ __forceinline__ void gemm_issue(int t, uint32_t st,
                                           const char* A, const char* B) {
#pragma unroll
    for (int i = 0; i < 8; i++) {
        int idx = t + i * 128;
        int row = idx >> 3, ch = idx & 7;
        cp_async16(st + row * SKB + ch * 16, A + (size_t)row * (DM * 2) + ch * 16);
        cp_async16(st + GTILE + row * SKB + ch * 16, B + (size_t)row * (DM * 2) + ch * 16);
    }
    CP_COMMIT();
}

template<int WHICH>
__global__ __launch_bounds__(128)
void mma_gemm_kernel(float* __restrict__ outp) {
    constexpr int NCH = 16;        // 16 chunks of BK=64
    extern __shared__ char dsm[];
    const uint32_t sbase = smem_u32(dsm);
    const int t = threadIdx.x, lane = t & 31, wid = t >> 5;
    const int nt = blockIdx.x, mt = blockIdx.y;
    const int m0 = mt * 128, n0 = nt * 128;

    const char* pA = (WHICH == 0) ? (const char*)g_x16h : (const char*)g_a16h;
    const char* pB = (WHICH == 0) ? (const char*)(g_w16 + (size_t)n0 * DM)
                                  : (const char*)(g_w16o + (size_t)n0 * DM);

    float acc[4][8][4];
#pragma unroll
    for (int a = 0; a < 4; a++)
#pragma unroll
        for (int b = 0; b < 8; b++)
#pragma unroll
            for (int c = 0; c < 4; c++) acc[a][b][c] = 0.f;

    // prologue: chunks 0,1 into ring buffers 0,1
#pragma unroll
    for (int c = 0; c < 2; c++) {
        gemm_issue(t, sbase + c * GSTAGE,
                   pA + (size_t)m0 * (DM * 2) + c * 128, pB + c * 128);
    }

    const int wm = wid & 1, wn = wid >> 1;      // 2x2 warps, 64x64 each
    const int q = lane >> 3, r = lane & 7;

    for (int c = 0; c < NCH; c++) {
        if (c + 1 < NCH) { CP_WAIT1(); } else { CP_WAIT0(); }
        __syncthreads();                          // all warps done with chunk c-1
        if (c + 2 < NCH) {                        // refill c-1's buffer with c+2
            int cn = c + 2;
            gemm_issue(t, sbase + (cn % 3) * GSTAGE,
                       pA + (size_t)m0 * (DM * 2) + cn * 128, pB + cn * 128);
        }

        const uint32_t sa = sbase + (c % 3) * GSTAGE + (wm * 64) * SKB;
        const uint32_t sb = sbase + (c % 3) * GSTAGE + GTILE + (wn * 64) * SKB;
#pragma unroll
        for (int ks = 0; ks < 4; ks++) {
            uint32_t af[4][4], bf[4][4];
#pragma unroll
            for (int mb = 0; mb < 4; mb++)
                ldsm_x4(af[mb], sa + (mb * 16 + (q & 1) * 8 + r) * SKB
                                   + (ks * 16 + (q >> 1) * 8) * 2);
#pragma unroll
            for (int np = 0; np < 4; np++)
                ldsm_x4(bf[np], sb + (np * 16 + (q >> 1) * 8 + r) * SKB
                                   + (ks * 16 + (q & 1) * 8) * 2);
#pragma unroll
            for (int mb = 0; mb < 4; mb++)
#pragma unroll
                for (int np = 0; np < 4; np++) {
                    mma16816h(acc[mb][np * 2],     af[mb], &bf[np][0]);
                    mma16816h(acc[mb][np * 2 + 1], af[mb], &bf[np][2]);
                }
        }
    }

    const int rr = lane >> 2, c2 = (lane & 3) * 2;
    if (WHICH == 1) {
#pragma unroll
        for (int mb = 0; mb < 4; mb++) {
            int row0 = m0 + wm * 64 + mb * 16 + rr;
#pragma unroll
            for (int nb = 0; nb < 8; nb++) {
                int col = n0 + wn * 64 + nb * 8 + c2;
                *(float2*)&outp[(size_t)row0 * DM + col]       = make_float2(acc[mb][nb][0], acc[mb][nb][1]);
                *(float2*)&outp[(size_t)(row0 + 8) * DM + col] = make_float2(acc[mb][nb][2], acc[mb][nb][3]);
            }
        }
    } else {
        const int mat = nt >> 3;                 // 0=Q 1=K 2=V
        const int ccol = (nt & 7) * 128;
        if (mat == 2) {
            // V: plain fp16 convert
#pragma unroll
            for (int mb = 0; mb < 4; mb++) {
                int row0 = m0 + wm * 64 + mb * 16 + rr;
#pragma unroll
                for (int nb = 0; nb < 8; nb++) {
                    int col = ccol + wn * 64 + nb * 8 + c2;
                    *(uint32_t*)&g_vh[(size_t)row0 * DM + col] =
                        packh2(__floats2half2_rn(acc[mb][nb][0], acc[mb][nb][1]));
                    *(uint32_t*)&g_vh[(size_t)(row0 + 8) * DM + col] =
                        packh2(__floats2half2_rn(acc[mb][nb][2], acc[mb][nb][3]));
                }
            }
        } else {
            // Q/K: apply RoPE in fp32, store fp16 (Q pre-scaled by log2e/8).
            // Warp 64-col span = one head; pair (i, i+32) = (nb, nb+4).
            __half* dst = (mat == 0) ? g_qh : g_kh;
            const float scale = (mat == 0) ? QSCALE : 1.f;
#pragma unroll
            for (int mb = 0; mb < 4; mb++) {
                int row0 = m0 + wm * 64 + mb * 16 + rr;
#pragma unroll
                for (int nb = 0; nb < 4; nb++) {
                    int i = nb * 8 + c2;                      // head-local col (0..31)
                    float4 t0 = *(float4*)&g_rope[row0][i * 2];        // cs_i sn_i cs_i1 sn_i1
                    float4 t1 = *(float4*)&g_rope[row0 + 8][i * 2];
                    int col_lo = ccol + wn * 64 + nb * 8 + c2;
                    int col_hi = col_lo + 32;
                    // row0, cols i / i+1
                    {
                        float a0 = acc[mb][nb][0], b0 = acc[mb][nb + 4][0];
                        float a1 = acc[mb][nb][1], b1 = acc[mb][nb + 4][1];
                        float lo0 = (a0 * t0.x - b0 * t0.y) * scale;
                        float hi0 = (b0 * t0.x + a0 * t0.y) * scale;
                        float lo1 = (a1 * t0.z - b1 * t0.w) * scale;
                        float hi1 = (b1 * t0.z + a1 * t0.w) * scale;
                        *(uint32_t*)&dst[(size_t)row0 * DM + col_lo] = packh2(__floats2half2_rn(lo0, lo1));
                        *(uint32_t*)&dst[(size_t)row0 * DM + col_hi] = packh2(__floats2half2_rn(hi0, hi1));
                    }
                    // row0+8
                    {
                        float a0 = acc[mb][nb][2], b0 = acc[mb][nb + 4][2];
                        float a1 = acc[mb][nb][3], b1 = acc[mb][nb + 4][3];
                        float lo0 = (a0 * t1.x - b0 * t1.y) * scale;
                        float hi0 = (b0 * t1.x + a0 * t1.y) * scale;
                        float lo1 = (a1 * t1.z - b1 * t1.w) * scale;
                        float hi1 = (b1 * t1.z + a1 * t1.w) * scale;
                        *(uint32_t*)&dst[(size_t)(row0 + 8) * DM + col_lo] = packh2(__floats2half2_rn(lo0, lo1));
                        *(uint32_t*)&dst[(size_t)(row0 + 8) * DM + col_hi] = packh2(__floats2half2_rn(hi0, hi1));
                    }
                }
            }
        }
    }
}

// ---------------- Flash attention: fp16 HMMA, exp2 softmax, 3-stage KV ------
// CTA = (q-tile 128 rows, head). 256 thr / 8 warps; warp = 16 q-rows x full 64 kv.
// V tile rows are 72 halves wide; cols 64..71 hold {1,0,...,0} -> row-sum via MMA.
#define F_STG 18432            // stage s at F_STG + s*F_STGSZ: Kh, Vh (9216 each)
#define F_T   9216
#define F_STGSZ 18432
#define FLASH_SMEM (18432 + 3 * F_STGSZ)   // 73728 -> 2 CTAs/SM (reg-limited)

__device__ __forceinline__ void flash_issue_kv(int t, uint32_t stg, int kbase, int h) {
    const size_t rowoff = (size_t)kbase * DM + h * 64;
    const __half* srcs[2] = {g_kh + rowoff, g_vh + rowoff};
#pragma unroll
    for (int i = 0; i < 4; i++) {
        int idx = t + i * 256;              // 0..1023
        int mat = idx >> 9;                 // 0..1
        int rem = idx & 511;
        int row = rem >> 3, ch = rem & 7;
        cp_async16(stg + mat * F_T + row * SKB + ch * 16,
                   (const char*)srcs[mat] + (size_t)row * (DM * 2) + ch * 16);
    }
    CP_COMMIT();
}

__global__ __launch_bounds__(256)
void flash_kernel() {
    extern __shared__ char dsm[];
    const uint32_t sbase = smem_u32(dsm);
    const int t = threadIdx.x, lane = t & 31, wid = t >> 5;
    const int h = blockIdx.y;
    const int qt = (int)gridDim.x - 1 - (int)blockIdx.x;   // heavy first
    const int qbase = qt * 128;
    const int ntiles = 2 * qt + 2;                          // >= 2

    // Prologue: Q + kv0 (one group), kv1 (second group)
    {
        const size_t rowoff = (size_t)qbase * DM + h * 64;
#pragma unroll
        for (int i = 0; i < 4; i++) {
            int idx = t + i * 256;           // 0..1023
            int row = idx >> 3, ch = idx & 7;
            cp_async16(sbase + row * SKB + ch * 16,
                       (const char*)(g_qh + rowoff) + (size_t)row * (DM * 2) + ch * 16);
        }
        flash_issue_kv(t, sbase + F_STG, 0, h);                // commits Q + kv0
        flash_issue_kv(t, sbase + F_STG + F_STGSZ, 64, h);     // kv1
    }

    // Ones-column pad for all 3 V stage buffers (bytes 128..143 of each V row;
    // cp.async only writes bytes 0..127, so this persists across stage reuse).
    if (t < 192) {
        int buf = t >> 6, row = t & 63;
        uint32_t off = F_STG + buf * F_STGSZ + F_T + row * SKB + 128;
        *(uint4*)(dsm + off) = make_uint4(0x00003C00u, 0u, 0u, 0u);  // half {1,0,..}
    }

    CP_WAIT1();          // Q + kv0 ready
    __syncthreads();     // (also publishes ones-pads)

    // preload Q fragments (persistent)
    const int q = lane >> 3, r = lane & 7;
    const int l16 = lane & 15;
    uint32_t qf[4][4];
#pragma unroll
    for (int ks = 0; ks < 4; ks++) {
        uint32_t ro = (wid * 16 + (q & 1) * 8 + r) * SKB + (ks * 16 + (q >> 1) * 8) * 2;
        ldsm_x4(qf[ks], sbase + ro);
    }
    // hoisted ones-column B fragment (identical for all tiles / k-steps)
    uint32_t bs_ones[2];
    ldsm_x2t(bs_ones, sbase + F_STG + F_T + l16 * SKB + 128);

    // issue kv2 into stage 2 (free) before computing tile 0
    if (ntiles > 2) flash_issue_kv(t, sbase + F_STG + 2 * F_STGSZ, 128, h);

    float o[8][4], o_sum[4];
#pragma unroll
    for (int a = 0; a < 8; a++)
#pragma unroll
        for (int b = 0; b < 4; b++) o[a][b] = 0.f;
#pragma unroll
    for (int b = 0; b < 4; b++) o_sum[b] = 0.f;
    float m0r = -1e30f, m1r = -1e30f;

    const int rr = lane >> 2, c2 = (lane & 3) * 2;
    const int qlo = qbase + wid * 16;
    const int qr0 = qlo + rr, qr1 = qr0 + 8;

    for (int kt = 0; kt < ntiles; kt++) {
        if (kt > 0) {
            if (kt + 1 < ntiles) { CP_WAIT1(); } else { CP_WAIT0(); }
            __syncthreads();                       // all warps done with tile kt-1
            if (kt + 2 < ntiles)                   // refill kt-1's stage with kt+2
                flash_issue_kv(t, sbase + F_STG + ((kt + 2) % 3) * F_STGSZ,
                               (kt + 2) * 64, h);
        }
        const uint32_t stg = sbase + F_STG + (kt % 3) * F_STGSZ;

        if (kt * 64 <= qlo + 15) {     // warp tile not fully masked
            float s[8][4];
#pragma unroll
            for (int a = 0; a < 8; a++)
#pragma unroll
                for (int b = 0; b < 4; b++) s[a][b] = 0.f;

            // S = Q * K (logits in log2 domain; Q pre-scaled by log2e/8)
#pragma unroll
            for (int ks = 0; ks < 4; ks++) {
#pragma unroll
                for (int np = 0; np < 4; np++) {
                    uint32_t kf[4];
                    uint32_t ro = (np * 16 + (q >> 1) * 8 + r) * SKB + (ks * 16 + (q & 1) * 8) * 2;
                    ldsm_x4(kf, stg + 0 * F_T + ro);
                    mma16816h(s[np * 2],     qf[ks], &kf[0]);
                    mma16816h(s[np * 2 + 1], qf[ks], &kf[2]);
                }
            }

            // causal mask (diagonal-straddling tiles only)
            if (kt * 64 + 63 > qlo) {
#pragma unroll
                for (int nb = 0; nb < 8; nb++) {
                    int kc = kt * 64 + nb * 8 + c2;
                    if (kc     > qr0) s[nb][0] = -1e30f;
                    if (kc + 1 > qr0) s[nb][1] = -1e30f;
                    if (kc     > qr1) s[nb][2] = -1e30f;
                    if (kc + 1 > qr1) s[nb][3] = -1e30f;
                }
            }

            // online max (log2 domain)
            float mx0 = -1e30f, mx1 = -1e30f;
#pragma unroll
            for (int nb = 0; nb < 8; nb++) {
                mx0 = fmaxf(mx0, fmaxf(s[nb][0], s[nb][1]));
                mx1 = fmaxf(mx1, fmaxf(s[nb][2], s[nb][3]));
            }
            mx0 = fmaxf(mx0, __shfl_xor_sync(0xffffffffu, mx0, 1));
            mx0 = fmaxf(mx0, __shfl_xor_sync(0xffffffffu, mx0, 2));
            mx1 = fmaxf(mx1, __shfl_xor_sync(0xffffffffu, mx1, 1));
            mx1 = fmaxf(mx1, __shfl_xor_sync(0xffffffffu, mx1, 2));
            float mn0 = fmaxf(m0r, mx0), mn1 = fmaxf(m1r, mx1);
            float al0 = exp2f(m0r - mn0), al1 = exp2f(m1r - mn1);
            m0r = mn0;  m1r = mn1;
#pragma unroll
            for (int nb = 0; nb < 8; nb++) {
                o[nb][0] *= al0; o[nb][1] *= al0;
                o[nb][2] *= al1; o[nb][3] *= al1;
            }
            o_sum[0] *= al0; o_sum[1] *= al0;
            o_sum[2] *= al1; o_sum[3] *= al1;

            // P = exp2(s - m) computed in fp16x2; PV (+ ones-column row sum)
#pragma unroll
            for (int ks = 0; ks < 4; ks++) {
                uint32_t ph[4];
#pragma unroll
                for (int hf = 0; hf < 2; hf++) {
                    int nb = 2 * ks + hf;
                    __half2 e0 = h2exp2(__floats2half2_rn(s[nb][0] - mn0, s[nb][1] - mn0));
                    __half2 e1 = h2exp2(__floats2half2_rn(s[nb][2] - mn1, s[nb][3] - mn1));
                    ph[hf * 2]     = packh2(e0);
                    ph[hf * 2 + 1] = packh2(e1);
                }
#pragma unroll
                for (int dp = 0; dp < 4; dp++) {
                    uint32_t vf[4];
                    uint32_t ro = (ks * 16 + (q & 1) * 8 + r) * SKB + (dp * 16 + (q >> 1) * 8) * 2;
                    ldsm_x4t(vf, stg + 1 * F_T + ro);
                    mma16816h(o[dp * 2],     ph, &vf[0]);
                    mma16816h(o[dp * 2 + 1], ph, &vf[2]);
                }
                mma16816h(o_sum, ph, bs_ones);
            }
        }
    }

    // epilogue: l lives in o_sum col 0 (lanes with lane&3==0); broadcast in quad
    float l0 = __shfl_sync(0xffffffffu, o_sum[0], lane & 0x1C);
    float l1 = __shfl_sync(0xffffffffu, o_sum[2], lane & 0x1C);
    float inv0 = 1.f / l0, inv1 = 1.f / l1;
#pragma unroll
    for (int nb = 0; nb < 8; nb++) {
        int col = h * 64 + nb * 8 + c2;
        *(uint32_t*)&g_a16h[(size_t)qr0 * DM + col] =
            packh2(__floats2half2_rn(o[nb][0] * inv0, o[nb][1] * inv0));
        *(uint32_t*)&g_a16h[(size_t)qr1 * DM + col] =
            packh2(__floats2half2_rn(o[nb][2] * inv1, o[nb][3] * inv1));
    }
}

// ---------------- launch ----------------
extern "C" void kernel_launch(void* const* d_in, const int* in_sizes, int n_in,
                              void* d_out, int out_size) {
    const float* x  = (const float*)d_in[0];
    const float* Wq = (const float*)d_in[1];
    const float* Wk = (const float*)d_in[2];
    const float* Wv = (const float*)d_in[3];
    const float* Wo = (const float*)d_in[4];
    float* out = (float*)d_out;

    cudaFuncSetAttribute(mma_gemm_kernel<0>, cudaFuncAttributeMaxDynamicSharedMemorySize, GEMM_SMEM);
    cudaFuncSetAttribute(mma_gemm_kernel<1>, cudaFuncAttributeMaxDynamicSharedMemorySize, GEMM_SMEM);
    cudaFuncSetAttribute(flash_kernel,       cudaFuncAttributeMaxDynamicSharedMemorySize, FLASH_SMEM);

    cvt_all_kernel<<<8704, 256>>>(x, Wq, Wk, Wv, Wo);

    mma_gemm_kernel<0><<<dim3(3 * DM / 128, SEQ / 128), 128, GEMM_SMEM>>>(nullptr);

    flash_kernel<<<dim3(SEQ / 128, NH), 256, FLASH_SMEM>>>();

    mma_gemm_kernel<1><<<dim3(DM / 128, SEQ / 128), 128, GEMM_SMEM>>>(out);
}

// round 12
// speedup vs baseline: 1.0442x; 1.0442x over previous
#include <cuda_runtime.h>
#include <cuda_fp16.h>
#include <math.h>
#include <stdint.h>

// Problem constants
#define SEQ   4096
#define DM    1024
#define NH    16
#define DH    64

// ---------------- scratch (no allocations allowed) ----------------
// QKV GEMM operands (fp16, 1-pass): x, W (Wq,Wk,Wv stacked rows)
__device__ __half g_x16h[SEQ * DM];
__device__ __half g_w16[3 * DM * DM];
// proj GEMM operands (fp16, 1-pass)
__device__ __half g_w16o[DM * DM];
__device__ __half g_a16h[SEQ * DM];        // attention out (fp16)

// flash operands (fp16), written directly by the QKV epilogue
__device__ __half g_qh[SEQ * DM];   // roped Q, pre-scaled by (1/8)*log2e
__device__ __half g_kh[SEQ * DM];   // roped K
__device__ __half g_vh[SEQ * DM];   // V

// rope table: [s][i*2]=cos, [i*2+1]=sin  (i = 0..31)
__device__ float g_rope[SEQ][64];

// ---------------- low-level helpers ----------------
__device__ __forceinline__ uint32_t smem_u32(const void* p) {
    uint32_t a;
    asm("{ .reg .u64 t; cvta.to.shared.u64 t, %1; cvt.u32.u64 %0, t; }" : "=r"(a) : "l"(p));
    return a;
}
__device__ __forceinline__ void cp_async16(uint32_t sa, const void* ga) {
    asm volatile("cp.async.cg.shared.global [%0], [%1], 16;" :: "r"(sa), "l"(ga));
}
#define CP_COMMIT() asm volatile("cp.async.commit_group;" ::: "memory")
#define CP_WAIT1()  asm volatile("cp.async.wait_group 1;" ::: "memory")
#define CP_WAIT0()  asm volatile("cp.async.wait_group 0;" ::: "memory")

__device__ __forceinline__ void ldsm_x4(uint32_t* r, uint32_t addr) {
    asm volatile("ldmatrix.sync.aligned.m8n8.x4.shared.b16 {%0,%1,%2,%3}, [%4];"
        : "=r"(r[0]), "=r"(r[1]), "=r"(r[2]), "=r"(r[3]) : "r"(addr));
}
__device__ __forceinline__ void ldsm_x4t(uint32_t* r, uint32_t addr) {
    asm volatile("ldmatrix.sync.aligned.m8n8.x4.trans.shared.b16 {%0,%1,%2,%3}, [%4];"
        : "=r"(r[0]), "=r"(r[1]), "=r"(r[2]), "=r"(r[3]) : "r"(addr));
}
__device__ __forceinline__ void ldsm_x2t(uint32_t* r, uint32_t addr) {
    asm volatile("ldmatrix.sync.aligned.m8n8.x2.trans.shared.b16 {%0,%1}, [%2];"
        : "=r"(r[0]), "=r"(r[1]) : "r"(addr));
}
// fp16 mma
__device__ __forceinline__ void mma16816h(float* d, const uint32_t* a, const uint32_t* b) {
    asm volatile("mma.sync.aligned.m16n8k16.row.col.f32.f16.f16.f32 "
        "{%0,%1,%2,%3}, {%4,%5,%6,%7}, {%8,%9}, {%0,%1,%2,%3};"
        : "+f"(d[0]), "+f"(d[1]), "+f"(d[2]), "+f"(d[3])
        : "r"(a[0]), "r"(a[1]), "r"(a[2]), "r"(a[3]), "r"(b[0]), "r"(b[1]));
}
__device__ __forceinline__ uint32_t packh2(__half2 v) {
    uint32_t u; memcpy(&u, &v, 4); return u;
}

// ---------------- fused convert + rope-table kernel (one launch) ----------
// b in [0,4096): x; [4096,7168): Wq/Wk/Wv (stacked); [7168,8192): Wo;
// b in [8192,8704): rope table.
__global__ void cvt_all_kernel(const float* __restrict__ x,
                               const float* __restrict__ Wq,
                               const float* __restrict__ Wk,
                               const float* __restrict__ Wv,
                               const float* __restrict__ Wo) {
    int b = blockIdx.x;
    if (b >= 8192) {
        int idx = (b - 8192) * 256 + threadIdx.x;   // 0..131071
        int s = idx >> 5, i = idx & 31;
        double invf = pow(10000.0, -(2.0 * i) / 64.0);
        double si, co;
        sincos((double)s * invf, &si, &co);
        g_rope[s][i * 2]     = (float)co;
        g_rope[s][i * 2 + 1] = (float)si;
        return;
    }
    const float* src; __half* dst; int si, di;
    if (b < 4096) {
        si = (b * 256 + threadIdx.x) * 4;
        di = si; src = x; dst = g_x16h;
    } else if (b < 7168) {
        int bb = b - 4096;                 // 0..3071
        int mat = bb >> 10;                // 0..2
        src = (mat == 0) ? Wq : (mat == 1 ? Wk : Wv);
        si = ((bb & 1023) * 256 + threadIdx.x) * 4;
        di = (bb * 256 + threadIdx.x) * 4;
        dst = g_w16;
    } else {
        si = ((b - 7168) * 256 + threadIdx.x) * 4;
        di = si; src = Wo; dst = g_w16o;
    }
    float4 v = *(const float4*)&src[si];
    *(uint32_t*)&dst[di]     = packh2(__floats2half2_rn(v.x, v.y));
    *(uint32_t*)&dst[di + 2] = packh2(__floats2half2_rn(v.z, v.w));
}

// ---------------- HMMA fp16 1-pass NT GEMM (2-stage, 3 CTAs/SM) ------------
// C[m,n] = sum_k A[m,k]*B[n,k]; BM=BN=128, BK=64, 128 threads, 4 warps of 64x64.
// WHICH=0: QKV; epilogue applies RoPE and stores fp16. WHICH=1: proj -> fp32 out.
#define SKB 144                    // smem row stride bytes (72 elems, conflict-free ldsm)
#define GTILE (128 * SKB)          // 18432 B per matrix tile
#define GSTAGE (2 * GTILE)         // A+B: 36864
#define GEMM_SMEM (2 * GSTAGE)     // double buffer: 73728 -> 3 CTAs/SM
#define QSCALE 0.18033688011112042f   // 0.125 * log2(e)

__device__ __forceinline__ void gemm_issue(int t, uint32_t st,
                                           const char* A, const char* B) {
#pragma unroll
    for (int i = 0; i < 8; i++) {
        int idx = t + i * 128;
        int row = idx >> 3, ch = idx & 7;
        cp_async16(st + row * SKB + ch * 16, A + (size_t)row * (DM * 2) + ch * 16);
        cp_async16(st + GTILE + row * SKB + ch * 16, B + (size_t)row * (DM * 2) + ch * 16);
    }
    CP_COMMIT();
}

template<int WHICH>
__global__ __launch_bounds__(128)
void mma_gemm_kernel(float* __restrict__ outp) {
    constexpr int NCH = 16;        // 16 chunks of BK=64
    extern __shared__ char dsm[];
    const uint32_t sbase = smem_u32(dsm);
    const int t = threadIdx.x, lane = t & 31, wid = t >> 5;
    const int nt = blockIdx.x, mt = blockIdx.y;
    const int m0 = mt * 128, n0 = nt * 128;

    const char* pA = (WHICH == 0) ? (const char*)g_x16h : (const char*)g_a16h;
    const char* pB = (WHICH == 0) ? (const char*)(g_w16 + (size_t)n0 * DM)
                                  : (const char*)(g_w16o + (size_t)n0 * DM);

    float acc[4][8][4];
#pragma unroll
    for (int a = 0; a < 4; a++)
#pragma unroll
        for (int b = 0; b < 8; b++)
#pragma unroll
            for (int c = 0; c < 4; c++) acc[a][b][c] = 0.f;

#pragma unroll
    for (int c = 0; c < 2; c++) {
        gemm_issue(t, sbase + (c & 1) * GSTAGE,
                   pA + (size_t)m0 * (DM * 2) + c * 128, pB + c * 128);
    }

    const int wm = wid & 1, wn = wid >> 1;      // 2x2 warps, 64x64 each
    const int q = lane >> 3, r = lane & 7;

    for (int c = 0; c < NCH; c++) {
        if (c + 1 < NCH) { CP_WAIT1(); } else { CP_WAIT0(); }
        __syncthreads();

        const uint32_t sa = sbase + (c & 1) * GSTAGE + (wm * 64) * SKB;
        const uint32_t sb = sbase + (c & 1) * GSTAGE + GTILE + (wn * 64) * SKB;
#pragma unroll
        for (int ks = 0; ks < 4; ks++) {
            uint32_t af[4][4], bf[4][4];
#pragma unroll
            for (int mb = 0; mb < 4; mb++)
                ldsm_x4(af[mb], sa + (mb * 16 + (q & 1) * 8 + r) * SKB
                                   + (ks * 16 + (q >> 1) * 8) * 2);
#pragma unroll
            for (int np = 0; np < 4; np++)
                ldsm_x4(bf[np], sb + (np * 16 + (q >> 1) * 8 + r) * SKB
                                   + (ks * 16 + (q & 1) * 8) * 2);
#pragma unroll
            for (int mb = 0; mb < 4; mb++)
#pragma unroll
                for (int np = 0; np < 4; np++) {
                    mma16816h(acc[mb][np * 2],     af[mb], &bf[np][0]);
                    mma16816h(acc[mb][np * 2 + 1], af[mb], &bf[np][2]);
                }
        }
        __syncthreads();
        if (c + 2 < NCH) {
            int cn = c + 2;
            gemm_issue(t, sbase + (cn & 1) * GSTAGE,
                       pA + (size_t)m0 * (DM * 2) + cn * 128, pB + cn * 128);
        }
    }

    const int rr = lane >> 2, c2 = (lane & 3) * 2;
    if (WHICH == 1) {
#pragma unroll
        for (int mb = 0; mb < 4; mb++) {
            int row0 = m0 + wm * 64 + mb * 16 + rr;
#pragma unroll
            for (int nb = 0; nb < 8; nb++) {
                int col = n0 + wn * 64 + nb * 8 + c2;
                *(float2*)&outp[(size_t)row0 * DM + col]       = make_float2(acc[mb][nb][0], acc[mb][nb][1]);
                *(float2*)&outp[(size_t)(row0 + 8) * DM + col] = make_float2(acc[mb][nb][2], acc[mb][nb][3]);
            }
        }
    } else {
        const int mat = nt >> 3;                 // 0=Q 1=K 2=V
        const int ccol = (nt & 7) * 128;
        if (mat == 2) {
            // V: plain fp16 convert
#pragma unroll
            for (int mb = 0; mb < 4; mb++) {
                int row0 = m0 + wm * 64 + mb * 16 + rr;
#pragma unroll
                for (int nb = 0; nb < 8; nb++) {
                    int col = ccol + wn * 64 + nb * 8 + c2;
                    *(uint32_t*)&g_vh[(size_t)row0 * DM + col] =
                        packh2(__floats2half2_rn(acc[mb][nb][0], acc[mb][nb][1]));
                    *(uint32_t*)&g_vh[(size_t)(row0 + 8) * DM + col] =
                        packh2(__floats2half2_rn(acc[mb][nb][2], acc[mb][nb][3]));
                }
            }
        } else {
            // Q/K: apply RoPE in fp32, store fp16 (Q pre-scaled by log2e/8).
            // Warp 64-col span = one head; pair (i, i+32) = (nb, nb+4).
            __half* dst = (mat == 0) ? g_qh : g_kh;
            const float scale = (mat == 0) ? QSCALE : 1.f;
#pragma unroll
            for (int mb = 0; mb < 4; mb++) {
                int row0 = m0 + wm * 64 + mb * 16 + rr;
#pragma unroll
                for (int nb = 0; nb < 4; nb++) {
                    int i = nb * 8 + c2;                      // head-local col (0..31)
                    float4 t0 = *(float4*)&g_rope[row0][i * 2];        // cs_i sn_i cs_i1 sn_i1
                    float4 t1 = *(float4*)&g_rope[row0 + 8][i * 2];
                    int col_lo = ccol + wn * 64 + nb * 8 + c2;
                    int col_hi = col_lo + 32;
                    {
                        float a0 = acc[mb][nb][0], b0 = acc[mb][nb + 4][0];
                        float a1 = acc[mb][nb][1], b1 = acc[mb][nb + 4][1];
                        float lo0 = (a0 * t0.x - b0 * t0.y) * scale;
                        float hi0 = (b0 * t0.x + a0 * t0.y) * scale;
                        float lo1 = (a1 * t0.z - b1 * t0.w) * scale;
                        float hi1 = (b1 * t0.z + a1 * t0.w) * scale;
                        *(uint32_t*)&dst[(size_t)row0 * DM + col_lo] = packh2(__floats2half2_rn(lo0, lo1));
                        *(uint32_t*)&dst[(size_t)row0 * DM + col_hi] = packh2(__floats2half2_rn(hi0, hi1));
                    }
                    {
                        float a0 = acc[mb][nb][2], b0 = acc[mb][nb + 4][2];
                        float a1 = acc[mb][nb][3], b1 = acc[mb][nb + 4][3];
                        float lo0 = (a0 * t1.x - b0 * t1.y) * scale;
                        float hi0 = (b0 * t1.x + a0 * t1.y) * scale;
                        float lo1 = (a1 * t1.z - b1 * t1.w) * scale;
                        float hi1 = (b1 * t1.z + a1 * t1.w) * scale;
                        *(uint32_t*)&dst[(size_t)(row0 + 8) * DM + col_lo] = packh2(__floats2half2_rn(lo0, lo1));
                        *(uint32_t*)&dst[(size_t)(row0 + 8) * DM + col_hi] = packh2(__floats2half2_rn(hi0, hi1));
                    }
                }
            }
        }
    }
}

// ---------------- Flash attention: fp16 HMMA, exp2 softmax, 3-stage KV ------
// CTA = (q-tile 128 rows, head). 256 thr / 8 warps; warp = 16 q-rows x full 64 kv.
// V tile rows are 72 halves wide; cols 64..71 hold {1,0,...,0} -> row-sum via MMA.
// Flash is register-limited to 2 CTAs/SM, so the 3rd stage is free smem; it buys
// one sync per tile and a full tile of cp.async lead.
#define F_STG 18432            // stage s at F_STG + s*F_STGSZ: Kh, Vh (9216 each)
#define F_T   9216
#define F_STGSZ 18432
#define FLASH_SMEM (18432 + 3 * F_STGSZ)   // 73728

__device__ __forceinline__ void flash_issue_kv(int t, uint32_t stg, int kbase, int h) {
    const size_t rowoff = (size_t)kbase * DM + h * 64;
    const __half* srcs[2] = {g_kh + rowoff, g_vh + rowoff};
#pragma unroll
    for (int i = 0; i < 4; i++) {
        int idx = t + i * 256;              // 0..1023
        int mat = idx >> 9;                 // 0..1
        int rem = idx & 511;
        int row = rem >> 3, ch = rem & 7;
        cp_async16(stg + mat * F_T + row * SKB + ch * 16,
                   (const char*)srcs[mat] + (size_t)row * (DM * 2) + ch * 16);
    }
    CP_COMMIT();
}

__global__ __launch_bounds__(256)
void flash_kernel() {
    extern __shared__ char dsm[];
    const uint32_t sbase = smem_u32(dsm);
    const int t = threadIdx.x, lane = t & 31, wid = t >> 5;
    const int h = blockIdx.y;
    const int qt = (int)gridDim.x - 1 - (int)blockIdx.x;   // heavy first
    const int qbase = qt * 128;
    const int ntiles = 2 * qt + 2;                          // >= 2

    // Prologue: Q + kv0 (one group), kv1 (second group)
    {
        const size_t rowoff = (size_t)qbase * DM + h * 64;
#pragma unroll
        for (int i = 0; i < 4; i++) {
            int idx = t + i * 256;           // 0..1023
            int row = idx >> 3, ch = idx & 7;
            cp_async16(sbase + row * SKB + ch * 16,
                       (const char*)(g_qh + rowoff) + (size_t)row * (DM * 2) + ch * 16);
        }
        flash_issue_kv(t, sbase + F_STG, 0, h);                // commits Q + kv0
        flash_issue_kv(t, sbase + F_STG + F_STGSZ, 64, h);     // kv1
    }

    // Ones-column pad for all 3 V stage buffers (bytes 128..143 of each V row;
    // cp.async only writes bytes 0..127, so this persists across stage reuse).
    if (t < 192) {
        int buf = t >> 6, row = t & 63;
        uint32_t off = F_STG + buf * F_STGSZ + F_T + row * SKB + 128;
        *(uint4*)(dsm + off) = make_uint4(0x00003C00u, 0u, 0u, 0u);  // half {1,0,..}
    }

    CP_WAIT1();          // Q + kv0 ready
    __syncthreads();     // (also publishes ones-pads)

    // preload Q fragments (persistent)
    const int q = lane >> 3, r = lane & 7;
    const int l16 = lane & 15;
    uint32_t qf[4][4];
#pragma unroll
    for (int ks = 0; ks < 4; ks++) {
        uint32_t ro = (wid * 16 + (q & 1) * 8 + r) * SKB + (ks * 16 + (q >> 1) * 8) * 2;
        ldsm_x4(qf[ks], sbase + ro);
    }
    // hoisted ones-column B fragment (identical for all tiles / k-steps)
    uint32_t bs_ones[2];
    ldsm_x2t(bs_ones, sbase + F_STG + F_T + l16 * SKB + 128);

    // issue kv2 into stage 2 (free) before computing tile 0
    if (ntiles > 2) flash_issue_kv(t, sbase + F_STG + 2 * F_STGSZ, 128, h);

    float o[8][4], o_sum[4];
#pragma unroll
    for (int a = 0; a < 8; a++)
#pragma unroll
        for (int b = 0; b < 4; b++) o[a][b] = 0.f;
#pragma unroll
    for (int b = 0; b < 4; b++) o_sum[b] = 0.f;
    float m0r = -1e30f, m1r = -1e30f;

    const int rr = lane >> 2, c2 = (lane & 3) * 2;
    const int qlo = qbase + wid * 16;
    const int qr0 = qlo + rr, qr1 = qr0 + 8;

    for (int kt = 0; kt < ntiles; kt++) {
        if (kt > 0) {
            if (kt + 1 < ntiles) { CP_WAIT1(); } else { CP_WAIT0(); }
            __syncthreads();                       // all warps done with tile kt-1
            if (kt + 2 < ntiles)                   // refill kt-1's stage with kt+2
                flash_issue_kv(t, sbase + F_STG + ((kt + 2) % 3) * F_STGSZ,
                               (kt + 2) * 64, h);
        }
        const uint32_t stg = sbase + F_STG + (kt % 3) * F_STGSZ;

        if (kt * 64 <= qlo + 15) {     // warp tile not fully masked
            float s[8][4];
#pragma unroll
            for (int a = 0; a < 8; a++)
#pragma unroll
                for (int b = 0; b < 4; b++) s[a][b] = 0.f;

            // S = Q * K (logits in log2 domain; Q pre-scaled by log2e/8)
#pragma unroll
            for (int ks = 0; ks < 4; ks++) {
#pragma unroll
                for (int np = 0; np < 4; np++) {
                    uint32_t kf[4];
                    uint32_t ro = (np * 16 + (q >> 1) * 8 + r) * SKB + (ks * 16 + (q & 1) * 8) * 2;
                    ldsm_x4(kf, stg + 0 * F_T + ro);
                    mma16816h(s[np * 2],     qf[ks], &kf[0]);
                    mma16816h(s[np * 2 + 1], qf[ks], &kf[2]);
                }
            }

            // causal mask (diagonal-straddling tiles only)
            if (kt * 64 + 63 > qlo) {
#pragma unroll
                for (int nb = 0; nb < 8; nb++) {
                    int kc = kt * 64 + nb * 8 + c2;
                    if (kc     > qr0) s[nb][0] = -1e30f;
                    if (kc + 1 > qr0) s[nb][1] = -1e30f;
                    if (kc     > qr1) s[nb][2] = -1e30f;
                    if (kc + 1 > qr1) s[nb][3] = -1e30f;
                }
            }

            // online max (log2 domain)
            float mx0 = -1e30f, mx1 = -1e30f;
#pragma unroll
            for (int nb = 0; nb < 8; nb++) {
                mx0 = fmaxf(mx0, fmaxf(s[nb][0], s[nb][1]));
                mx1 = fmaxf(mx1, fmaxf(s[nb][2], s[nb][3]));
            }
            mx0 = fmaxf(mx0, __shfl_xor_sync(0xffffffffu, mx0, 1));
            mx0 = fmaxf(mx0, __shfl_xor_sync(0xffffffffu, mx0, 2));
            mx1 = fmaxf(mx1, __shfl_xor_sync(0xffffffffu, mx1, 1));
            mx1 = fmaxf(mx1, __shfl_xor_sync(0xffffffffu, mx1, 2));
            float mn0 = fmaxf(m0r, mx0), mn1 = fmaxf(m1r, mx1);
            float al0 = exp2f(m0r - mn0), al1 = exp2f(m1r - mn1);
            m0r = mn0;  m1r = mn1;
#pragma unroll
            for (int nb = 0; nb < 8; nb++) {
                o[nb][0] *= al0; o[nb][1] *= al0;
                o[nb][2] *= al1; o[nb][3] *= al1;
            }
            o_sum[0] *= al0; o_sum[1] *= al0;
            o_sum[2] *= al1; o_sum[3] *= al1;

            // P = exp2(s - m) computed in fp16x2; PV (+ ones-column row sum)
#pragma unroll
            for (int ks = 0; ks < 4; ks++) {
                uint32_t ph[4];
#pragma unroll
                for (int hf = 0; hf < 2; hf++) {
                    int nb = 2 * ks + hf;
                    __half2 e0 = h2exp2(__floats2half2_rn(s[nb][0] - mn0, s[nb][1] - mn0));
                    __half2 e1 = h2exp2(__floats2half2_rn(s[nb][2] - mn1, s[nb][3] - mn1));
                    ph[hf * 2]     = packh2(e0);
                    ph[hf * 2 + 1] = packh2(e1);
                }
#pragma unroll
                for (int dp = 0; dp < 4; dp++) {
                    uint32_t vf[4];
                    uint32_t ro = (ks * 16 + (q & 1) * 8 + r) * SKB + (dp * 16 + (q >> 1) * 8) * 2;
                    ldsm_x4t(vf, stg + 1 * F_T + ro);
                    mma16816h(o[dp * 2],     ph, &vf[0]);
                    mma16816h(o[dp * 2 + 1], ph, &vf[2]);
                }
                mma16816h(o_sum, ph, bs_ones);
            }
        }
    }

    // epilogue: l lives in o_sum col 0 (lanes with lane&3==0); broadcast in quad
    float l0 = __shfl_sync(0xffffffffu, o_sum[0], lane & 0x1C);
    float l1 = __shfl_sync(0xffffffffu, o_sum[2], lane & 0x1C);
    float inv0 = 1.f / l0, inv1 = 1.f / l1;
#pragma unroll
    for (int nb = 0; nb < 8; nb++) {
        int col = h * 64 + nb * 8 + c2;
        *(uint32_t*)&g_a16h[(size_t)qr0 * DM + col] =
            packh2(__floats2half2_rn(o[nb][0] * inv0, o[nb][1] * inv0));
        *(uint32_t*)&g_a16h[(size_t)qr1 * DM + col] =
            packh2(__floats2half2_rn(o[nb][2] * inv1, o[nb][3] * inv1));
    }
}

// ---------------- launch ----------------
extern "C" void kernel_launch(void* const* d_in, const int* in_sizes, int n_in,
                              void* d_out, int out_size) {
    const float* x  = (const float*)d_in[0];
    const float* Wq = (const float*)d_in[1];
    const float* Wk = (const float*)d_in[2];
    const float* Wv = (const float*)d_in[3];
    const float* Wo = (const float*)d_in[4];
    float* out = (float*)d_out;

    cudaFuncSetAttribute(mma_gemm_kernel<0>, cudaFuncAttributeMaxDynamicSharedMemorySize, GEMM_SMEM);
    cudaFuncSetAttribute(mma_gemm_kernel<1>, cudaFuncAttributeMaxDynamicSharedMemorySize, GEMM_SMEM);
    cudaFuncSetAttribute(flash_kernel,       cudaFuncAttributeMaxDynamicSharedMemorySize, FLASH_SMEM);

    cvt_all_kernel<<<8704, 256>>>(x, Wq, Wk, Wv, Wo);

    mma_gemm_kernel<0><<<dim3(3 * DM / 128, SEQ / 128), 128, GEMM_SMEM>>>(nullptr);

    flash_kernel<<<dim3(SEQ / 128, NH), 256, FLASH_SMEM>>>();

    mma_gemm_kernel<1><<<dim3(DM / 128, SEQ / 128), 128, GEMM_SMEM>>>(out);
}

// round 13
// speedup vs baseline: 1.0991x; 1.0526x over previous
#include <cuda_runtime.h>
#include <cuda_fp16.h>
#include <math.h>
#include <stdint.h>

// Problem constants
#define SEQ   4096
#define DM    1024
#define NH    16
#define DH    64

// ---------------- scratch (no allocations allowed) ----------------
// QKV GEMM operands (fp16, 1-pass): x, W (Wq,Wk,Wv stacked rows)
__device__ __half g_x16h[SEQ * DM];
__device__ __half g_w16[3 * DM * DM];
// proj GEMM operands (fp16, 1-pass)
__device__ __half g_w16o[DM * DM];
__device__ __half g_a16h[SEQ * DM];        // attention out (fp16)

// flash operands (fp16), written directly by the QKV epilogue
__device__ __half g_qh[SEQ * DM];   // roped Q, pre-scaled by (1/8)*log2e
__device__ __half g_kh[SEQ * DM];   // roped K
__device__ __half g_vh[SEQ * DM];   // V

// rope table: [s][i*2]=cos, [i*2+1]=sin  (i = 0..31)
__device__ float g_rope[SEQ][64];

// ---------------- low-level helpers ----------------
__device__ __forceinline__ uint32_t smem_u32(const void* p) {
    uint32_t a;
    asm("{ .reg .u64 t; cvta.to.shared.u64 t, %1; cvt.u32.u64 %0, t; }" : "=r"(a) : "l"(p));
    return a;
}
__device__ __forceinline__ void cp_async16(uint32_t sa, const void* ga) {
    asm volatile("cp.async.cg.shared.global [%0], [%1], 16;" :: "r"(sa), "l"(ga));
}
#define CP_COMMIT() asm volatile("cp.async.commit_group;" ::: "memory")
#define CP_WAIT1()  asm volatile("cp.async.wait_group 1;" ::: "memory")
#define CP_WAIT0()  asm volatile("cp.async.wait_group 0;" ::: "memory")

__device__ __forceinline__ void ldsm_x4(uint32_t* r, uint32_t addr) {
    asm volatile("ldmatrix.sync.aligned.m8n8.x4.shared.b16 {%0,%1,%2,%3}, [%4];"
        : "=r"(r[0]), "=r"(r[1]), "=r"(r[2]), "=r"(r[3]) : "r"(addr));
}
__device__ __forceinline__ void ldsm_x4t(uint32_t* r, uint32_t addr) {
    asm volatile("ldmatrix.sync.aligned.m8n8.x4.trans.shared.b16 {%0,%1,%2,%3}, [%4];"
        : "=r"(r[0]), "=r"(r[1]), "=r"(r[2]), "=r"(r[3]) : "r"(addr));
}
__device__ __forceinline__ void ldsm_x2t(uint32_t* r, uint32_t addr) {
    asm volatile("ldmatrix.sync.aligned.m8n8.x2.trans.shared.b16 {%0,%1}, [%2];"
        : "=r"(r[0]), "=r"(r[1]) : "r"(addr));
}
// fp16 mma
__device__ __forceinline__ void mma16816h(float* d, const uint32_t* a, const uint32_t* b) {
    asm volatile("mma.sync.aligned.m16n8k16.row.col.f32.f16.f16.f32 "
        "{%0,%1,%2,%3}, {%4,%5,%6,%7}, {%8,%9}, {%0,%1,%2,%3};"
        : "+f"(d[0]), "+f"(d[1]), "+f"(d[2]), "+f"(d[3])
        : "r"(a[0]), "r"(a[1]), "r"(a[2]), "r"(a[3]), "r"(b[0]), "r"(b[1]));
}
__device__ __forceinline__ uint32_t packh2(__half2 v) {
    uint32_t u; memcpy(&u, &v, 4); return u;
}

// ---------------- rope table (double-precision sincos, fp32 store) ----------
__global__ void rope_tab_kernel() {
    int idx = blockIdx.x * 256 + threadIdx.x;   // 0..131071
    int s = idx >> 5, i = idx & 31;
    double invf = pow(10000.0, -(2.0 * i) / 64.0);
    double si, co;
    sincos((double)s * invf, &si, &co);
    g_rope[s][i * 2]     = (float)co;
    g_rope[s][i * 2 + 1] = (float)si;
}

// ---------------- fused convert kernel (all 5 inputs, one launch) ----------
// b in [0,4096): x; [4096,7168): Wq/Wk/Wv (stacked); [7168,8192): Wo.
__global__ void cvt_all_kernel(const float* __restrict__ x,
                               const float* __restrict__ Wq,
                               const float* __restrict__ Wk,
                               const float* __restrict__ Wv,
                               const float* __restrict__ Wo) {
    int b = blockIdx.x;
    const float* src; __half* dst; int si, di;
    if (b < 4096) {
        si = (b * 256 + threadIdx.x) * 4;
        di = si; src = x; dst = g_x16h;
    } else if (b < 7168) {
        int bb = b - 4096;                 // 0..3071
        int mat = bb >> 10;                // 0..2
        src = (mat == 0) ? Wq : (mat == 1 ? Wk : Wv);
        si = ((bb & 1023) * 256 + threadIdx.x) * 4;
        di = (bb * 256 + threadIdx.x) * 4;
        dst = g_w16;
    } else {
        si = ((b - 7168) * 256 + threadIdx.x) * 4;
        di = si; src = Wo; dst = g_w16o;
    }
    float4 v = *(const float4*)&src[si];
    *(uint32_t*)&dst[di]     = packh2(__floats2half2_rn(v.x, v.y));
    *(uint32_t*)&dst[di + 2] = packh2(__floats2half2_rn(v.z, v.w));
}

// ---------------- HMMA fp16 1-pass NT GEMM (256 thr, 32x64 warp tiles) -----
// C[m,n] = sum_k A[m,k]*B[n,k]; BM=BN=128, BK=64, 256 threads.
// Warps 4(M)x2(N): warp tile 32x64 -> 64 acc regs/thread -> <=128 regs ->
// 2 CTAs x 8 warps = 16 warps/SM (vs 12 before).
// WHICH=0: QKV; epilogue applies RoPE and stores fp16. WHICH=1: proj -> fp32 out.
#define SKB 144                    // smem row stride bytes (72 elems, conflict-free ldsm)
#define GTILE (128 * SKB)          // 18432 B per matrix tile
#define GSTAGE (2 * GTILE)         // A+B: 36864
#define GEMM_SMEM (2 * GSTAGE)     // double buffer: 73728 -> 2 CTAs/SM
#define QSCALE 0.18033688011112042f   // 0.125 * log2(e)

__device__ __forceinline__ void gemm_issue256(int t, uint32_t st,
                                              const char* A, const char* B) {
#pragma unroll
    for (int i = 0; i < 4; i++) {
        int idx = t + i * 256;             // 0..1023
        int row = idx >> 3, ch = idx & 7;
        cp_async16(st + row * SKB + ch * 16, A + (size_t)row * (DM * 2) + ch * 16);
    }
#pragma unroll
    for (int i = 0; i < 4; i++) {
        int idx = t + i * 256;
        int row = idx >> 3, ch = idx & 7;
        cp_async16(st + GTILE + row * SKB + ch * 16, B + (size_t)row * (DM * 2) + ch * 16);
    }
    CP_COMMIT();
}

template<int WHICH>
__global__ __launch_bounds__(256, 2)
void mma_gemm_kernel(float* __restrict__ outp) {
    constexpr int NCH = 16;        // 16 chunks of BK=64
    extern __shared__ char dsm[];
    const uint32_t sbase = smem_u32(dsm);
    const int t = threadIdx.x, lane = t & 31, wid = t >> 5;
    const int nt = blockIdx.x, mt = blockIdx.y;
    const int m0 = mt * 128, n0 = nt * 128;

    const char* pA = (WHICH == 0) ? (const char*)g_x16h : (const char*)g_a16h;
    const char* pB = (WHICH == 0) ? (const char*)(g_w16 + (size_t)n0 * DM)
                                  : (const char*)(g_w16o + (size_t)n0 * DM);

    float acc[2][8][4];
#pragma unroll
    for (int a = 0; a < 2; a++)
#pragma unroll
        for (int b = 0; b < 8; b++)
#pragma unroll
            for (int c = 0; c < 4; c++) acc[a][b][c] = 0.f;

#pragma unroll
    for (int c = 0; c < 2; c++) {
        gemm_issue256(t, sbase + (c & 1) * GSTAGE,
                      pA + (size_t)m0 * (DM * 2) + c * 128, pB + c * 128);
    }

    const int wm = wid & 3, wn = wid >> 2;      // 4x2 warps, 32x64 each
    const int q = lane >> 3, r = lane & 7;

    for (int c = 0; c < NCH; c++) {
        if (c + 1 < NCH) { CP_WAIT1(); } else { CP_WAIT0(); }
        __syncthreads();

        const uint32_t sa = sbase + (c & 1) * GSTAGE + (wm * 32) * SKB;
        const uint32_t sb = sbase + (c & 1) * GSTAGE + GTILE + (wn * 64) * SKB;
#pragma unroll
        for (int ks = 0; ks < 4; ks++) {
            uint32_t af[2][4], bf[4][4];
#pragma unroll
            for (int mb = 0; mb < 2; mb++)
                ldsm_x4(af[mb], sa + (mb * 16 + (q & 1) * 8 + r) * SKB
                                   + (ks * 16 + (q >> 1) * 8) * 2);
#pragma unroll
            for (int np = 0; np < 4; np++)
                ldsm_x4(bf[np], sb + (np * 16 + (q >> 1) * 8 + r) * SKB
                                   + (ks * 16 + (q & 1) * 8) * 2);
#pragma unroll
            for (int mb = 0; mb < 2; mb++)
#pragma unroll
                for (int np = 0; np < 4; np++) {
                    mma16816h(acc[mb][np * 2],     af[mb], &bf[np][0]);
                    mma16816h(acc[mb][np * 2 + 1], af[mb], &bf[np][2]);
                }
        }
        __syncthreads();
        if (c + 2 < NCH) {
            int cn = c + 2;
            gemm_issue256(t, sbase + (cn & 1) * GSTAGE,
                          pA + (size_t)m0 * (DM * 2) + cn * 128, pB + cn * 128);
        }
    }

    const int rr = lane >> 2, c2 = (lane & 3) * 2;
    if (WHICH == 1) {
#pragma unroll
        for (int mb = 0; mb < 2; mb++) {
            int row0 = m0 + wm * 32 + mb * 16 + rr;
#pragma unroll
            for (int nb = 0; nb < 8; nb++) {
                int col = n0 + wn * 64 + nb * 8 + c2;
                *(float2*)&outp[(size_t)row0 * DM + col]       = make_float2(acc[mb][nb][0], acc[mb][nb][1]);
                *(float2*)&outp[(size_t)(row0 + 8) * DM + col] = make_float2(acc[mb][nb][2], acc[mb][nb][3]);
            }
        }
    } else {
        const int mat = nt >> 3;                 // 0=Q 1=K 2=V
        const int ccol = (nt & 7) * 128;
        if (mat == 2) {
            // V: plain fp16 convert
#pragma unroll
            for (int mb = 0; mb < 2; mb++) {
                int row0 = m0 + wm * 32 + mb * 16 + rr;
#pragma unroll
                for (int nb = 0; nb < 8; nb++) {
                    int col = ccol + wn * 64 + nb * 8 + c2;
                    *(uint32_t*)&g_vh[(size_t)row0 * DM + col] =
                        packh2(__floats2half2_rn(acc[mb][nb][0], acc[mb][nb][1]));
                    *(uint32_t*)&g_vh[(size_t)(row0 + 8) * DM + col] =
                        packh2(__floats2half2_rn(acc[mb][nb][2], acc[mb][nb][3]));
                }
            }
        } else {
            // Q/K: apply RoPE in fp32, store fp16 (Q pre-scaled by log2e/8).
            // Warp 64-col span = one head; pair (i, i+32) = (nb, nb+4).
            __half* dst = (mat == 0) ? g_qh : g_kh;
            const float scale = (mat == 0) ? QSCALE : 1.f;
#pragma unroll
            for (int mb = 0; mb < 2; mb++) {
                int row0 = m0 + wm * 32 + mb * 16 + rr;
#pragma unroll
                for (int nb = 0; nb < 4; nb++) {
                    int i = nb * 8 + c2;                      // head-local col (0..31)
                    float4 t0 = *(float4*)&g_rope[row0][i * 2];        // cs_i sn_i cs_i1 sn_i1
                    float4 t1 = *(float4*)&g_rope[row0 + 8][i * 2];
                    int col_lo = ccol + wn * 64 + nb * 8 + c2;
                    int col_hi = col_lo + 32;
                    {
                        float a0 = acc[mb][nb][0], b0 = acc[mb][nb + 4][0];
                        float a1 = acc[mb][nb][1], b1 = acc[mb][nb + 4][1];
                        float lo0 = (a0 * t0.x - b0 * t0.y) * scale;
                        float hi0 = (b0 * t0.x + a0 * t0.y) * scale;
                        float lo1 = (a1 * t0.z - b1 * t0.w) * scale;
                        float hi1 = (b1 * t0.z + a1 * t0.w) * scale;
                        *(uint32_t*)&dst[(size_t)row0 * DM + col_lo] = packh2(__floats2half2_rn(lo0, lo1));
                        *(uint32_t*)&dst[(size_t)row0 * DM + col_hi] = packh2(__floats2half2_rn(hi0, hi1));
                    }
                    {
                        float a0 = acc[mb][nb][2], b0 = acc[mb][nb + 4][2];
                        float a1 = acc[mb][nb][3], b1 = acc[mb][nb + 4][3];
                        float lo0 = (a0 * t1.x - b0 * t1.y) * scale;
                        float hi0 = (b0 * t1.x + a0 * t1.y) * scale;
                        float lo1 = (a1 * t1.z - b1 * t1.w) * scale;
                        float hi1 = (b1 * t1.z + a1 * t1.w) * scale;
                        *(uint32_t*)&dst[(size_t)(row0 + 8) * DM + col_lo] = packh2(__floats2half2_rn(lo0, lo1));
                        *(uint32_t*)&dst[(size_t)(row0 + 8) * DM + col_hi] = packh2(__floats2half2_rn(hi0, hi1));
                    }
                }
            }
        }
    }
}

// ---------------- Flash attention (EXACT round-10 form: 2-stage KV) ---------
// CTA = (q-tile 128 rows, head). 256 thr / 8 warps; warp = 16 q-rows x full 64 kv.
// V tile rows are 72 halves wide; cols 64..71 hold {1,0,...,0} -> row-sum via MMA.
#define F_STG 18432            // stage s at F_STG + s*F_STGSZ: Kh, Vh (9216 each)
#define F_T   9216
#define F_STGSZ 18432
#define FLASH_SMEM (18432 + 2 * F_STGSZ)   // 55296

__device__ __forceinline__ void flash_issue_kv(int t, uint32_t stg, int kbase, int h) {
    const size_t rowoff = (size_t)kbase * DM + h * 64;
    const __half* srcs[2] = {g_kh + rowoff, g_vh + rowoff};
#pragma unroll
    for (int i = 0; i < 4; i++) {
        int idx = t + i * 256;              // 0..1023
        int mat = idx >> 9;                 // 0..1
        int rem = idx & 511;
        int row = rem >> 3, ch = rem & 7;
        cp_async16(stg + mat * F_T + row * SKB + ch * 16,
                   (const char*)srcs[mat] + (size_t)row * (DM * 2) + ch * 16);
    }
    CP_COMMIT();
}

__global__ __launch_bounds__(256)
void flash_kernel() {
    extern __shared__ char dsm[];
    const uint32_t sbase = smem_u32(dsm);
    const int t = threadIdx.x, lane = t & 31, wid = t >> 5;
    const int h = blockIdx.y;
    const int qt = (int)gridDim.x - 1 - (int)blockIdx.x;   // heavy first
    const int qbase = qt * 128;
    const int ntiles = 2 * qt + 2;

    // Q load + kv tile0 (one group), then kv tile1
    {
        const size_t rowoff = (size_t)qbase * DM + h * 64;
#pragma unroll
        for (int i = 0; i < 4; i++) {
            int idx = t + i * 256;           // 0..1023
            int row = idx >> 3, ch = idx & 7;
            cp_async16(sbase + row * SKB + ch * 16,
                       (const char*)(g_qh + rowoff) + (size_t)row * (DM * 2) + ch * 16);
        }
        flash_issue_kv(t, sbase + F_STG, 0, h);            // commits Q + tile0
        flash_issue_kv(t, sbase + F_STG + F_STGSZ, 64, h); // tile 1
    }

    // Ones-column pad for both V stage buffers (bytes 128..143 of each V row;
    // cp.async only writes bytes 0..127, so this persists across stage reuse).
    if (t < 128) {
        int buf = t >> 6, row = t & 63;
        uint32_t off = F_STG + buf * F_STGSZ + F_T + row * SKB + 128;
        *(uint4*)(dsm + off) = make_uint4(0x00003C00u, 0u, 0u, 0u);  // half {1,0,...,0}
    }

    CP_WAIT1();          // Q + tile0 ready
    __syncthreads();

    // preload Q fragments (persistent)
    const int q = lane >> 3, r = lane & 7;
    const int l16 = lane & 15;
    uint32_t qf[4][4];
#pragma unroll
    for (int ks = 0; ks < 4; ks++) {
        uint32_t ro = (wid * 16 + (q & 1) * 8 + r) * SKB + (ks * 16 + (q >> 1) * 8) * 2;
        ldsm_x4(qf[ks], sbase + ro);
    }
    // hoisted ones-column B fragment (identical for all tiles / k-steps)
    uint32_t bs_ones[2];
    ldsm_x2t(bs_ones, sbase + F_STG + F_T + l16 * SKB + 128);

    float o[8][4], o_sum[4];
#pragma unroll
    for (int a = 0; a < 8; a++)
#pragma unroll
        for (int b = 0; b < 4; b++) o[a][b] = 0.f;
#pragma unroll
    for (int b = 0; b < 4; b++) o_sum[b] = 0.f;
    float m0r = -1e30f, m1r = -1e30f;

    const int rr = lane >> 2, c2 = (lane & 3) * 2;
    const int qlo = qbase + wid * 16;
    const int qr0 = qlo + rr, qr1 = qr0 + 8;

    for (int kt = 0; kt < ntiles; kt++) {
        const uint32_t stg = sbase + F_STG + (kt & 1) * F_STGSZ;

        if (kt * 64 <= qlo + 15) {     // warp tile not fully masked
            float s[8][4];
#pragma unroll
            for (int a = 0; a < 8; a++)
#pragma unroll
                for (int b = 0; b < 4; b++) s[a][b] = 0.f;

            // S = Q * K (logits in log2 domain; Q pre-scaled by log2e/8)
#pragma unroll
            for (int ks = 0; ks < 4; ks++) {
#pragma unroll
                for (int np = 0; np < 4; np++) {
                    uint32_t kf[4];
                    uint32_t ro = (np * 16 + (q >> 1) * 8 + r) * SKB + (ks * 16 + (q & 1) * 8) * 2;
                    ldsm_x4(kf, stg + 0 * F_T + ro);
                    mma16816h(s[np * 2],     qf[ks], &kf[0]);
                    mma16816h(s[np * 2 + 1], qf[ks], &kf[2]);
                }
            }

            // causal mask (diagonal-straddling tiles only)
            if (kt * 64 + 63 > qlo) {
#pragma unroll
                for (int nb = 0; nb < 8; nb++) {
                    int kc = kt * 64 + nb * 8 + c2;
                    if (kc     > qr0) s[nb][0] = -1e30f;
                    if (kc + 1 > qr0) s[nb][1] = -1e30f;
                    if (kc     > qr1) s[nb][2] = -1e30f;
                    if (kc + 1 > qr1) s[nb][3] = -1e30f;
                }
            }

            // online max (log2 domain)
            float mx0 = -1e30f, mx1 = -1e30f;
#pragma unroll
            for (int nb = 0; nb < 8; nb++) {
                mx0 = fmaxf(mx0, fmaxf(s[nb][0], s[nb][1]));
                mx1 = fmaxf(mx1, fmaxf(s[nb][2], s[nb][3]));
            }
            mx0 = fmaxf(mx0, __shfl_xor_sync(0xffffffffu, mx0, 1));
            mx0 = fmaxf(mx0, __shfl_xor_sync(0xffffffffu, mx0, 2));
            mx1 = fmaxf(mx1, __shfl_xor_sync(0xffffffffu, mx1, 1));
            mx1 = fmaxf(mx1, __shfl_xor_sync(0xffffffffu, mx1, 2));
            float mn0 = fmaxf(m0r, mx0), mn1 = fmaxf(m1r, mx1);
            float al0 = exp2f(m0r - mn0), al1 = exp2f(m1r - mn1);
            m0r = mn0;  m1r = mn1;
#pragma unroll
            for (int nb = 0; nb < 8; nb++) {
                o[nb][0] *= al0; o[nb][1] *= al0;
                o[nb][2] *= al1; o[nb][3] *= al1;
            }
            o_sum[0] *= al0; o_sum[1] *= al0;
            o_sum[2] *= al1; o_sum[3] *= al1;

            // P = exp2(s - m) computed in fp16x2; PV (+ ones-column row sum)
#pragma unroll
            for (int ks = 0; ks < 4; ks++) {
                uint32_t ph[4];
#pragma unroll
                for (int hf = 0; hf < 2; hf++) {
                    int nb = 2 * ks + hf;
                    __half2 e0 = h2exp2(__floats2half2_rn(s[nb][0] - mn0, s[nb][1] - mn0));
                    __half2 e1 = h2exp2(__floats2half2_rn(s[nb][2] - mn1, s[nb][3] - mn1));
                    ph[hf * 2]     = packh2(e0);
                    ph[hf * 2 + 1] = packh2(e1);
                }
#pragma unroll
                for (int dp = 0; dp < 4; dp++) {
                    uint32_t vf[4];
                    uint32_t ro = (ks * 16 + (q & 1) * 8 + r) * SKB + (dp * 16 + (q >> 1) * 8) * 2;
                    ldsm_x4t(vf, stg + 1 * F_T + ro);
                    mma16816h(o[dp * 2],     ph, &vf[0]);
                    mma16816h(o[dp * 2 + 1], ph, &vf[2]);
                }
                mma16816h(o_sum, ph, bs_ones);
            }
        }

        __syncthreads();          // done reading this stage
        if (kt + 2 < ntiles)
            flash_issue_kv(t, sbase + F_STG + (kt & 1) * F_STGSZ, (kt + 2) * 64, h);
        if (kt + 1 < ntiles) {
            if (kt + 2 < ntiles) { CP_WAIT1(); } else { CP_WAIT0(); }
            __syncthreads();      // tile kt+1 data visible to all
        }
    }

    // epilogue: l lives in o_sum col 0 (lanes with lane&3==0); broadcast in quad
    float l0 = __shfl_sync(0xffffffffu, o_sum[0], lane & 0x1C);
    float l1 = __shfl_sync(0xffffffffu, o_sum[2], lane & 0x1C);
    float inv0 = 1.f / l0, inv1 = 1.f / l1;
#pragma unroll
    for (int nb = 0; nb < 8; nb++) {
        int col = h * 64 + nb * 8 + c2;
        *(uint32_t*)&g_a16h[(size_t)qr0 * DM + col] =
            packh2(__floats2half2_rn(o[nb][0] * inv0, o[nb][1] * inv0));
        *(uint32_t*)&g_a16h[(size_t)qr1 * DM + col] =
            packh2(__floats2half2_rn(o[nb][2] * inv1, o[nb][3] * inv1));
    }
}

// ---------------- launch ----------------
extern "C" void kernel_launch(void* const* d_in, const int* in_sizes, int n_in,
                              void* d_out, int out_size) {
    const float* x  = (const float*)d_in[0];
    const float* Wq = (const float*)d_in[1];
    const float* Wk = (const float*)d_in[2];
    const float* Wv = (const float*)d_in[3];
    const float* Wo = (const float*)d_in[4];
    float* out = (float*)d_out;

    cudaFuncSetAttribute(mma_gemm_kernel<0>, cudaFuncAttributeMaxDynamicSharedMemorySize, GEMM_SMEM);
    cudaFuncSetAttribute(mma_gemm_kernel<1>, cudaFuncAttributeMaxDynamicSharedMemorySize, GEMM_SMEM);
    cudaFuncSetAttribute(flash_kernel,       cudaFuncAttributeMaxDynamicSharedMemorySize, FLASH_SMEM);

    rope_tab_kernel<<<512, 256>>>();
    cvt_all_kernel<<<8192, 256>>>(x, Wq, Wk, Wv, Wo);

    mma_gemm_kernel<0><<<dim3(3 * DM / 128, SEQ / 128), 256, GEMM_SMEM>>>(nullptr);

    flash_kernel<<<dim3(SEQ / 128, NH), 256, FLASH_SMEM>>>();

    mma_gemm_kernel<1><<<dim3(DM / 128, SEQ / 128), 256, GEMM_SMEM>>>(out);
}